// round 3
// baseline (speedup 1.0000x reference)
#include <cuda_runtime.h>
#include <cuda_bf16.h>
#include <float.h>

// Problem constants (from reference setup_inputs)
#define Bq 4
#define Tq 512
#define Uq 65
#define Lq 64
#define Vq 1024
#define ROWS (Bq * Tq * Uq)     // 133120
#define NEGF (-1.0e30f)

// Scratch: lp_blank[b][t][u], lp_label[b][t][u] (label slot u==64 unused)
__device__ float g_lpb[ROWS];
__device__ float g_lpl[ROWS];

// ---------------------------------------------------------------------------
// Kernel 1: per (b,t,u) row of V=1024, compute logsumexp and extract
// x[blank]-lse and x[target[u]]-lse. One warp per row, single memory pass.
// ---------------------------------------------------------------------------
__global__ __launch_bounds__(256) void rna_lse_kernel(
    const float* __restrict__ logits,
    const int*   __restrict__ targets)
{
    int gw   = (blockIdx.x * blockDim.x + threadIdx.x) >> 5;  // global warp = row
    int lane = threadIdx.x & 31;
    if (gw >= ROWS) return;

    int b = gw / (Tq * Uq);
    int u = gw % Uq;

    // target element index for this row (only meaningful for u < L)
    int lab = 0;
    if (u < Lq) lab = targets[b * Lq + u];
    int tvec  = lab >> 2;
    int town  = tvec & 31;   // owner lane
    int tc    = tvec >> 5;   // chunk
    int tcomp = lab & 3;

    const float4* p = reinterpret_cast<const float4*>(logits) + (size_t)gw * 256;

    float4 v[8];
    float xlab = 0.0f, xblank = 0.0f;
    float mx = -FLT_MAX;
#pragma unroll
    for (int c = 0; c < 8; c++) {
        v[c] = p[c * 32 + lane];
        if (c == 0 && lane == 0) xblank = v[c].x;
        if (c == tc && lane == town) {
            float4 w = v[c];
            xlab = (tcomp == 0) ? w.x : (tcomp == 1) ? w.y : (tcomp == 2) ? w.z : w.w;
        }
        mx = fmaxf(mx, fmaxf(fmaxf(v[c].x, v[c].y), fmaxf(v[c].z, v[c].w)));
    }
#pragma unroll
    for (int off = 16; off > 0; off >>= 1)
        mx = fmaxf(mx, __shfl_xor_sync(0xffffffffu, mx, off));

    float s = 0.0f;
#pragma unroll
    for (int c = 0; c < 8; c++) {
        s += __expf(v[c].x - mx) + __expf(v[c].y - mx)
           + __expf(v[c].z - mx) + __expf(v[c].w - mx);
    }
#pragma unroll
    for (int off = 16; off > 0; off >>= 1)
        s += __shfl_xor_sync(0xffffffffu, s, off);

    float lse = mx + __logf(s);

    if (lane == 0)               g_lpb[gw] = xblank - lse;
    if (u < Lq && lane == town)  g_lpl[gw] = xlab - lse;
}

// ---------------------------------------------------------------------------
// Kernel 2: forward DP. One warp per batch element, 65 lattice states mapped
// to one warp (lane -> u, u+32; lane0 -> u=64). Shuffle-only recurrence,
// register double-buffered loads (chunk 4) to hide L2 latency.
// ---------------------------------------------------------------------------
__device__ __forceinline__ float lae(float a, float bx) {
    float mxv = fmaxf(a, bx);
    float mnv = fminf(a, bx);
    return mxv + __logf(1.0f + __expf(mnv - mxv));
}

__global__ __launch_bounds__(128) void rna_dp_kernel(
    const int* __restrict__ fbank_len,
    const int* __restrict__ text_len,
    float*     __restrict__ out)
{
    const int w    = threadIdx.x >> 5;   // batch index
    const int lane = threadIdx.x & 31;
    const unsigned FULL = 0xffffffffu;

    __shared__ float ll_s[Bq];

    const float* pb = g_lpb + (size_t)w * Tq * Uq;
    const float* pl = g_lpl + (size_t)w * Tq * Uq;
    int fb = fbank_len[w];
    int tl = text_len[w];

    // alpha0
    float aA = (lane == 0) ? 0.0f : NEGF;  // u = lane
    float aB = NEGF;                        // u = lane + 32
    float aC = NEGF;                        // u = 64 (lane 0)
    float ll = NEGF;
    if (fb == 0) ll = (tl == 0) ? 0.0f : NEGF;

    const int CH = 4;
    float cb0[CH], cb1[CH], cb2[CH], cl0[CH], cl1[CH], cl2[CH];
    float nb0[CH], nb1[CH], nb2[CH], nl0[CH], nl1[CH], nl2[CH];

    int laneL0 = (lane == 0) ? 0 : (lane - 1);

#pragma unroll
    for (int i = 0; i < CH; i++) {
        int tt = min(i, Tq - 1);
        const float* rb = pb + tt * Uq;
        const float* rl = pl + tt * Uq;
        cb0[i] = rb[lane];      cb1[i] = rb[32 + lane]; cb2[i] = rb[64];
        cl0[i] = rl[laneL0];    cl1[i] = rl[31 + lane]; cl2[i] = rl[63];
    }

    for (int tc = 0; tc < fb; tc += CH) {
        // prefetch next chunk (clamped)
#pragma unroll
        for (int i = 0; i < CH; i++) {
            int tt = min(tc + CH + i, Tq - 1);
            const float* rb = pb + tt * Uq;
            const float* rl = pl + tt * Uq;
            nb0[i] = rb[lane];   nb1[i] = rb[32 + lane]; nb2[i] = rb[64];
            nl0[i] = rl[laneL0]; nl1[i] = rl[31 + lane]; nl2[i] = rl[63];
        }
#pragma unroll
        for (int i = 0; i < CH; i++) {
            int t = tc + i;
            if (t < fb) {
                float prevA = __shfl_up_sync(FULL, aA, 1);   // alpha[lane-1]
                float a31   = __shfl_sync(FULL, aA, 31);     // alpha[31]
                float prevB = __shfl_up_sync(FULL, aB, 1);   // alpha[lane+31]
                float a63   = __shfl_sync(FULL, aB, 31);     // alpha[63]

                float moveA = (lane == 0) ? NEGF : (prevA + cl0[i]);
                float pBv   = (lane == 0) ? a31 : prevB;
                float moveB = pBv + cl1[i];

                float nA = lae(aA + cb0[i], moveA);
                float nB = lae(aB + cb1[i], moveB);
                float nC = lae(aC + cb2[i], a63 + cl2[i]);
                aA = nA; aB = nB; aC = nC;

                if (t + 1 == fb) {
                    float vv;
                    if (tl < 32)       vv = __shfl_sync(FULL, aA, tl);
                    else if (tl < 64)  vv = __shfl_sync(FULL, aB, tl - 32);
                    else               vv = __shfl_sync(FULL, aC, 0);
                    if (lane == 0) ll = vv;
                }
            }
        }
#pragma unroll
        for (int i = 0; i < CH; i++) {
            cb0[i] = nb0[i]; cb1[i] = nb1[i]; cb2[i] = nb2[i];
            cl0[i] = nl0[i]; cl1[i] = nl1[i]; cl2[i] = nl2[i];
        }
    }

    if (lane == 0) ll_s[w] = ll;
    __syncthreads();
    if (threadIdx.x == 0) {
        float s = ll_s[0] + ll_s[1] + ll_s[2] + ll_s[3];
        out[0] = -s * (1.0f / Bq);
    }
}

// ---------------------------------------------------------------------------
extern "C" void kernel_launch(void* const* d_in, const int* in_sizes, int n_in,
                              void* d_out, int out_size) {
    const float* logits  = (const float*)d_in[0];
    const int*   targets = (const int*)d_in[1];
    const int*   fbank   = (const int*)d_in[2];
    const int*   tlen    = (const int*)d_in[3];
    float*       out     = (float*)d_out;

    // 8 warps (rows) per block
    int blocks = (ROWS + 7) / 8;
    rna_lse_kernel<<<blocks, 256>>>(logits, targets);
    rna_dp_kernel<<<1, 128>>>(fbank, tlen, out);
}